// round 1
// baseline (speedup 1.0000x reference)
#include <cuda_runtime.h>
#include <cstdint>

// Problem constants (fixed by the reference)
#define MAXN 100000
#define MAXE 3200000
#define INF  256
#define OUTF 64
#define ALPHA 0.2f

// Static scratch (no allocation allowed)
__device__ float g_h[(size_t)MAXN * OUTF];   // 25.6 MB
__device__ float g_s1[MAXN];
__device__ float g_s2[MAXN];
__device__ int   g_m[MAXN];                  // segment max (ordered-int encoding)
__device__ float g_den[MAXN];                // segment sum of exp
__device__ float g_e[MAXE];                  // e, then reused for exp(e-m)
__device__ int   g_src[MAXE];
__device__ int   g_dst[MAXE];
__device__ int   g_is64;

// Monotonic float <-> int encoding for atomicMax on signed int
__device__ __forceinline__ int fenc(float f) {
    int i = __float_as_int(f);
    return i >= 0 ? i : (i ^ 0x7fffffff);
}
__device__ __forceinline__ float fdec(int i) {
    return __int_as_float(i >= 0 ? i : (i ^ 0x7fffffff));
}

// ---------------------------------------------------------------------------
// Detect whether adj is int64 (high 32-bit words all zero) or int32.
// ---------------------------------------------------------------------------
__global__ void k_detect(const int* __restrict__ adj32, int E) {
    __shared__ int sh[256];
    int t = threadIdx.x;
    int acc = 0;
#pragma unroll
    for (int j = 0; j < 4; j++) {
        int idx = 2 * (t * 4 + j) + 1;  // odd 32-bit slots = int64 high words
        if (idx < 2 * E) acc |= adj32[idx];
    }
    sh[t] = acc;
    __syncthreads();
    for (int s = 128; s; s >>= 1) {
        if (t < s) sh[t] |= sh[t + s];
        __syncthreads();
    }
    if (t == 0) g_is64 = (sh[0] == 0) ? 1 : 0;
}

__global__ void k_convert(const void* __restrict__ adj, int E) {
    int i = blockIdx.x * blockDim.x + threadIdx.x;
    if (i >= E) return;
    if (g_is64) {
        const long long* a = (const long long*)adj;
        g_src[i] = (int)a[i];
        g_dst[i] = (int)a[(size_t)i + E];
    } else {
        const int* a = (const int*)adj;
        g_src[i] = a[i];
        g_dst[i] = a[(size_t)i + E];
    }
}

__global__ void k_init(float* __restrict__ out, int N) {
    int i = blockIdx.x * blockDim.x + threadIdx.x;
    if (i < N * OUTF) out[i] = 0.0f;
    if (i < N) {
        g_m[i]   = (int)0x80000000;  // below any fenc(float)
        g_den[i] = 0.0f;
    }
}

// ---------------------------------------------------------------------------
// GEMM: h[N,64] = x[N,256] @ W[64,256]^T + b;  also s1 = h@a1, s2 = h@a2.
// 256 threads: thread t -> output o = t&63, K-chunk kc = t>>6 (64 K each).
// W chunk lives in registers; x tiled through smem (8 nodes / tile).
// ---------------------------------------------------------------------------
__global__ void __launch_bounds__(256) k_gemm(
    const float* __restrict__ x, const float* __restrict__ W,
    const float* __restrict__ b, const float* __restrict__ a, int N)
{
    __shared__ float4 xs[8][64];       // 8 nodes x 256 floats
    __shared__ float  red[8][4][64];   // partial dots per (node, kc, o)
    __shared__ float  sp[4][2][2];     // s1/s2 warp partials per node-group

    int t  = threadIdx.x;
    int o  = t & 63;
    int kc = t >> 6;

    float Wreg[64];
    const float4* wp = (const float4*)(W + (size_t)o * INF + kc * 64);
#pragma unroll
    for (int i = 0; i < 16; i++) {
        float4 w = __ldg(wp + i);
        Wreg[4 * i + 0] = w.x; Wreg[4 * i + 1] = w.y;
        Wreg[4 * i + 2] = w.z; Wreg[4 * i + 3] = w.w;
    }
    float bo  = __ldg(b + o);
    float a1o = __ldg(a + o);
    float a2o = __ldg(a + OUTF + o);

    int nTiles = (N + 7) >> 3;
    for (int tile = blockIdx.x; tile < nTiles; tile += gridDim.x) {
        int base = tile * 8;
        // Phase A: load x tile (coalesced float4)
#pragma unroll
        for (int r = 0; r < 2; r++) {
            int idx = t + 256 * r;
            int nn = idx >> 6, c = idx & 63;
            int node = base + nn;
            float4 v = make_float4(0.f, 0.f, 0.f, 0.f);
            if (node < N) v = __ldg((const float4*)(x + (size_t)node * INF) + c);
            xs[nn][c] = v;
        }
        __syncthreads();
        // Phase B: partial dot over this thread's 64-K chunk for 8 nodes
#pragma unroll
        for (int nn = 0; nn < 8; nn++) {
            const float4* xp = &xs[nn][kc * 16];
            float acc = 0.f;
#pragma unroll
            for (int i = 0; i < 16; i++) {
                float4 xv = xp[i];  // warp-broadcast (same addr across warp)
                acc += xv.x * Wreg[4 * i + 0] + xv.y * Wreg[4 * i + 1]
                     + xv.z * Wreg[4 * i + 2] + xv.w * Wreg[4 * i + 3];
            }
            red[nn][kc][o] = acc;
        }
        __syncthreads();
        // Phase C: combine K-chunks, add bias, store h, reduce s1/s2
#pragma unroll
        for (int rep = 0; rep < 2; rep++) {
            int g    = t >> 6;          // node group 0..3
            int nn   = rep * 4 + g;
            int node = base + nn;
            float h = red[nn][0][o] + red[nn][1][o] + red[nn][2][o] + red[nn][3][o] + bo;
            if (node < N) g_h[(size_t)node * OUTF + o] = h;
            float p1 = h * a1o, p2 = h * a2o;
#pragma unroll
            for (int off = 16; off; off >>= 1) {
                p1 += __shfl_down_sync(0xffffffffu, p1, off);
                p2 += __shfl_down_sync(0xffffffffu, p2, off);
            }
            int w = t >> 5, half = w & 1;
            if ((t & 31) == 0) { sp[g][half][0] = p1; sp[g][half][1] = p2; }
            __syncthreads();
            if (t < 4) {
                int node2 = base + rep * 4 + t;
                if (node2 < N) {
                    g_s1[node2] = sp[t][0][0] + sp[t][1][0];
                    g_s2[node2] = sp[t][0][1] + sp[t][1][1];
                }
            }
            __syncthreads();
        }
    }
}

// ---------------------------------------------------------------------------
// Edge pass 1: e = leakyrelu(s1[src] + s2[dst]); segment max over dst
// ---------------------------------------------------------------------------
__global__ void k_edge1(int E) {
    int i = blockIdx.x * blockDim.x + threadIdx.x;
    if (i >= E) return;
    int s = g_src[i], d = g_dst[i];
    float e = g_s1[s] + g_s2[d];
    e = e > 0.f ? e : ALPHA * e;
    g_e[i] = e;
    atomicMax(&g_m[d], fenc(e));
}

// Edge pass 2: ex = exp(e - m[dst]); segment sum over dst
__global__ void k_edge2(int E) {
    int i = blockIdx.x * blockDim.x + threadIdx.x;
    if (i >= E) return;
    int d = g_dst[i];
    float ex = __expf(g_e[i] - fdec(g_m[d]));
    g_e[i] = ex;
    atomicAdd(&g_den[d], ex);
}

// ---------------------------------------------------------------------------
// Edge pass 3: out[src] += (ex/denom[dst]) * h[dst]  (64 floats/edge)
// 16 lanes per edge, each lane handles one float4 slice via vector RED.
// ---------------------------------------------------------------------------
__global__ void k_edge3(float* __restrict__ out, int E) {
    long long gid = (long long)blockIdx.x * blockDim.x + threadIdx.x;
    int e = (int)(gid >> 4);
    if (e >= E) return;
    int sub = (int)(gid & 15);
    int s = g_src[e], d = g_dst[e];
    float att = g_e[e] / g_den[d];
    float4 hv = __ldg((const float4*)(g_h + (size_t)d * OUTF) + sub);
    float4 v;
    v.x = att * hv.x; v.y = att * hv.y; v.z = att * hv.z; v.w = att * hv.w;
    float* p = out + (size_t)s * OUTF + sub * 4;
    asm volatile("red.global.add.v4.f32 [%0], {%1, %2, %3, %4};"
                 :: "l"(p), "f"(v.x), "f"(v.y), "f"(v.z), "f"(v.w)
                 : "memory");
}

// ELU epilogue (alpha = 1): x > 0 ? x : exp(x) - 1
__global__ void k_elu(float* __restrict__ out, int N) {
    int i = blockIdx.x * blockDim.x + threadIdx.x;
    if (i >= N * OUTF) return;
    float v = out[i];
    out[i] = v > 0.f ? v : expm1f(v);
}

extern "C" void kernel_launch(void* const* d_in, const int* in_sizes, int n_in,
                              void* d_out, int out_size)
{
    const void*  adj = d_in[0];
    const float* x   = (const float*)d_in[1];
    const float* W   = (const float*)d_in[2];
    const float* b   = (const float*)d_in[3];
    const float* a   = (const float*)d_in[4];
    float* out = (float*)d_out;

    int E = in_sizes[0] / 2;
    int N = in_sizes[1] / INF;

    k_detect<<<1, 256>>>((const int*)adj, E);
    k_convert<<<(E + 255) / 256, 256>>>(adj, E);
    k_init<<<(N * OUTF + 255) / 256, 256>>>(out, N);
    k_gemm<<<1024, 256>>>(x, W, b, a, N);
    k_edge1<<<(E + 255) / 256, 256>>>(E);
    k_edge2<<<(E + 255) / 256, 256>>>(E);
    long long total3 = (long long)E * 16;
    k_edge3<<<(int)((total3 + 255) / 256), 256>>>(out, E);
    k_elu<<<(N * OUTF + 255) / 256, 256>>>(out, N);
}

// round 2
// speedup vs baseline: 1.3182x; 1.3182x over previous
#include <cuda_runtime.h>
#include <cstdint>

#define MAXN 100000
#define MAXE 3200000
#define INF  256
#define OUTF 64
#define ALPHA 0.2f

// Static scratch (no allocation allowed)
__device__ float g_h[(size_t)MAXN * OUTF];   // 25.6 MB
__device__ float g_s1[MAXN];
__device__ float g_s2[MAXN];
__device__ float g_den[MAXN];                // segment sum of exp
__device__ float g_e[MAXE];                  // exp(e)
__device__ int   g_src[MAXE];
__device__ int   g_dst[MAXE];
__device__ float g_wt[INF * OUTF];           // W transposed [k][o]
__device__ int   g_is64;

// ---------------------------------------------------------------------------
// Detect whether adj is int64 (high 32-bit words all zero) or int32.
// ---------------------------------------------------------------------------
__global__ void k_detect(const int* __restrict__ adj32, int E) {
    __shared__ int sh[256];
    int t = threadIdx.x;
    int acc = 0;
#pragma unroll
    for (int j = 0; j < 4; j++) {
        int idx = 2 * (t * 4 + j) + 1;  // odd 32-bit slots = int64 high words
        if (idx < 2 * E) acc |= adj32[idx];
    }
    sh[t] = acc;
    __syncthreads();
    for (int s = 128; s; s >>= 1) {
        if (t < s) sh[t] |= sh[t + s];
        __syncthreads();
    }
    if (t == 0) g_is64 = (sh[0] == 0) ? 1 : 0;
}

// Transpose W [64][256] -> g_wt [256][64] (tiny, one-shot)
__global__ void k_wt(const float* __restrict__ W) {
    int i = blockIdx.x * blockDim.x + threadIdx.x;
    if (i < INF * OUTF) {
        int k = i >> 6, o = i & 63;
        g_wt[i] = W[o * INF + k];
    }
}

__global__ void k_init(float* __restrict__ out, int N) {
    int i = blockIdx.x * blockDim.x + threadIdx.x;
    if (i < N * OUTF) out[i] = 0.0f;
    if (i < N) g_den[i] = 0.0f;
}

// ---------------------------------------------------------------------------
// Register-tiled SGEMM: h[N,64] = x[N,256] @ W^T + b; fused s1 = h@a1, s2 = h@a2.
// Block: 256 threads (16x16), tile M=64 nodes x N=64 outs, 4x4 micro-tile.
// W staged in smem in two 128-K halves (32KB); x tiles double-buffered.
// ---------------------------------------------------------------------------
#define XS_STRIDE 68
__global__ void __launch_bounds__(256) k_gemm(
    const float* __restrict__ x, const float* __restrict__ b,
    const float* __restrict__ a, int N)
{
    __shared__ float Ws[128 * 64];              // 32 KB: half of Wt
    __shared__ float xs[2][16 * XS_STRIDE];     // 8.5 KB: [kk][m] with pad

    int t  = threadIdx.x;
    int tx = t & 15;        // n-group: n0 = tx*4
    int ty = t >> 4;        // m-group: m0 = ty*4
    int base = blockIdx.x * 64;

    int m_l = t >> 2, q_l = t & 3;   // x-tile loader mapping

    float4 acc[4];
#pragma unroll
    for (int i = 0; i < 4; i++) acc[i] = make_float4(0.f, 0.f, 0.f, 0.f);

    const float4* xrow = (const float4*)(x + (size_t)(base + m_l) * INF);
    bool mvalid = (base + m_l) < N;

#pragma unroll
    for (int half = 0; half < 2; half++) {
        // Stage this half of Wt: 128 k x 64 o = 8192 floats, coalesced float4
        {
            const float4* wp = (const float4*)(g_wt + half * 128 * 64);
            float4* wsp = (float4*)Ws;
#pragma unroll
            for (int i = 0; i < 8; i++) wsp[t + 256 * i] = __ldg(wp + t + 256 * i);
        }
        // Preload first x chunk of this half
        {
            float4 v = make_float4(0.f, 0.f, 0.f, 0.f);
            if (mvalid) v = __ldg(xrow + (half * 8) * 4 + q_l);
            float* dst = xs[0];
            dst[(q_l * 4 + 0) * XS_STRIDE + m_l] = v.x;
            dst[(q_l * 4 + 1) * XS_STRIDE + m_l] = v.y;
            dst[(q_l * 4 + 2) * XS_STRIDE + m_l] = v.z;
            dst[(q_l * 4 + 3) * XS_STRIDE + m_l] = v.w;
        }
        __syncthreads();

#pragma unroll
        for (int kc = 0; kc < 8; kc++) {
            int buf = kc & 1;
            if (kc < 7) {   // prefetch next chunk into other buffer
                float4 v = make_float4(0.f, 0.f, 0.f, 0.f);
                if (mvalid) v = __ldg(xrow + (half * 8 + kc + 1) * 4 + q_l);
                float* dst = xs[buf ^ 1];
                dst[(q_l * 4 + 0) * XS_STRIDE + m_l] = v.x;
                dst[(q_l * 4 + 1) * XS_STRIDE + m_l] = v.y;
                dst[(q_l * 4 + 2) * XS_STRIDE + m_l] = v.z;
                dst[(q_l * 4 + 3) * XS_STRIDE + m_l] = v.w;
            }
#pragma unroll
            for (int kk = 0; kk < 16; kk++) {
                float4 bv = *(const float4*)&Ws[(kc * 16 + kk) * 64 + tx * 4];
                float4 av = *(const float4*)&xs[buf][kk * XS_STRIDE + ty * 4];
                acc[0].x += av.x * bv.x; acc[0].y += av.x * bv.y;
                acc[0].z += av.x * bv.z; acc[0].w += av.x * bv.w;
                acc[1].x += av.y * bv.x; acc[1].y += av.y * bv.y;
                acc[1].z += av.y * bv.z; acc[1].w += av.y * bv.w;
                acc[2].x += av.z * bv.x; acc[2].y += av.z * bv.y;
                acc[2].z += av.z * bv.z; acc[2].w += av.z * bv.w;
                acc[3].x += av.w * bv.x; acc[3].y += av.w * bv.y;
                acc[3].z += av.w * bv.z; acc[3].w += av.w * bv.w;
            }
            __syncthreads();
        }
    }

    // Epilogue: bias, store h, fused s1/s2 reduction
    float4 b4  = __ldg((const float4*)b + tx);
    float4 a1v = __ldg((const float4*)a + tx);
    float4 a2v = __ldg((const float4*)(a + OUTF) + tx);

#pragma unroll
    for (int mi = 0; mi < 4; mi++) {
        int node = base + ty * 4 + mi;
        float4 h;
        h.x = acc[mi].x + b4.x; h.y = acc[mi].y + b4.y;
        h.z = acc[mi].z + b4.z; h.w = acc[mi].w + b4.w;
        if (node < N)
            *((float4*)(g_h + (size_t)node * OUTF) + tx) = h;
        float p1 = h.x * a1v.x + h.y * a1v.y + h.z * a1v.z + h.w * a1v.w;
        float p2 = h.x * a2v.x + h.y * a2v.y + h.z * a2v.z + h.w * a2v.w;
#pragma unroll
        for (int off = 8; off; off >>= 1) {
            p1 += __shfl_xor_sync(0xffffffffu, p1, off);
            p2 += __shfl_xor_sync(0xffffffffu, p2, off);
        }
        if (tx == 0 && node < N) {
            g_s1[node] = p1;
            g_s2[node] = p2;
        }
    }
}

// ---------------------------------------------------------------------------
// Fused edge pass: convert adj, e = leakyrelu(s1[src]+s2[dst]),
// ex = exp(e) (no max shift needed: |e| << 88), denom atomicAdd.
// ---------------------------------------------------------------------------
__global__ void k_edge12(const void* __restrict__ adj, int E) {
    int i = blockIdx.x * blockDim.x + threadIdx.x;
    if (i >= E) return;
    int s, d;
    if (g_is64) {
        const long long* a = (const long long*)adj;
        s = (int)a[i];
        d = (int)a[(size_t)i + E];
    } else {
        const int* a = (const int*)adj;
        s = a[i];
        d = a[(size_t)i + E];
    }
    g_src[i] = s;
    g_dst[i] = d;
    float e = g_s1[s] + g_s2[d];
    e = e > 0.f ? e : ALPHA * e;
    float ex = __expf(e);
    g_e[i] = ex;
    atomicAdd(&g_den[d], ex);
}

// ---------------------------------------------------------------------------
// Edge pass 3: out[src] += (ex/denom[dst]) * h[dst]  (64 floats/edge)
// 16 lanes per edge, vector RED per float4 slice.
// ---------------------------------------------------------------------------
__global__ void k_edge3(float* __restrict__ out, int E) {
    long long gid = (long long)blockIdx.x * blockDim.x + threadIdx.x;
    int e = (int)(gid >> 4);
    if (e >= E) return;
    int sub = (int)(gid & 15);
    int s = g_src[e], d = g_dst[e];
    float att = g_e[e] / g_den[d];
    float4 hv = __ldg((const float4*)(g_h + (size_t)d * OUTF) + sub);
    float4 v;
    v.x = att * hv.x; v.y = att * hv.y; v.z = att * hv.z; v.w = att * hv.w;
    float* p = out + (size_t)s * OUTF + sub * 4;
    asm volatile("red.global.add.v4.f32 [%0], {%1, %2, %3, %4};"
                 :: "l"(p), "f"(v.x), "f"(v.y), "f"(v.z), "f"(v.w)
                 : "memory");
}

// ELU epilogue (alpha = 1)
__global__ void k_elu(float* __restrict__ out, int N) {
    int i = blockIdx.x * blockDim.x + threadIdx.x;
    if (i >= N * OUTF) return;
    float v = out[i];
    out[i] = v > 0.f ? v : expm1f(v);
}

extern "C" void kernel_launch(void* const* d_in, const int* in_sizes, int n_in,
                              void* d_out, int out_size)
{
    const void*  adj = d_in[0];
    const float* x   = (const float*)d_in[1];
    const float* W   = (const float*)d_in[2];
    const float* b   = (const float*)d_in[3];
    const float* a   = (const float*)d_in[4];
    float* out = (float*)d_out;

    int E = in_sizes[0] / 2;
    int N = in_sizes[1] / INF;

    k_detect<<<1, 256>>>((const int*)adj, E);
    k_wt<<<(INF * OUTF + 255) / 256, 256>>>(W);
    k_init<<<(N * OUTF + 255) / 256, 256>>>(out, N);
    k_gemm<<<(N + 63) / 64, 256>>>(x, b, a, N);
    k_edge12<<<(E + 255) / 256, 256>>>(adj, E);
    long long total3 = (long long)E * 16;
    k_edge3<<<(int)((total3 + 255) / 256), 256>>>(out, E);
    k_elu<<<(N * OUTF + 255) / 256, 256>>>(out, N);
}

// round 3
// speedup vs baseline: 1.5557x; 1.1802x over previous
#include <cuda_runtime.h>
#include <cstdint>

#define MAXN 100000
#define MAXE 3200000
#define INF  256
#define OUTF 64
#define ALPHA 0.2f

// Static scratch
__device__ float g_h[(size_t)MAXN * OUTF];   // 25.6 MB
__device__ float g_s1[MAXN];
__device__ float g_s2[MAXN];
__device__ float g_den[MAXN];
__device__ float g_e[MAXE];                  // exp(e)
__device__ int   g_src[MAXE];
__device__ int   g_dst[MAXE];
__device__ int   g_deg[MAXN];                // degree by src
__device__ int   g_ptr[MAXN];                // CSR row starts
__device__ int   g_cur[MAXN];                // scatter cursors
__device__ int   g_bsum[128];                // scan partials
__device__ int   g_sdst[MAXE];               // dst sorted by src
__device__ float g_satt[MAXE];               // att sorted by src
__device__ float g_wt[INF * OUTF];           // W transposed [k][o]
__device__ int   g_is64;

// ---------------------------------------------------------------------------
__global__ void k_detect(const int* __restrict__ adj32, int E) {
    __shared__ int sh[256];
    int t = threadIdx.x;
    int acc = 0;
#pragma unroll
    for (int j = 0; j < 4; j++) {
        int idx = 2 * (t * 4 + j) + 1;
        if (idx < 2 * E) acc |= adj32[idx];
    }
    sh[t] = acc;
    __syncthreads();
    for (int s = 128; s; s >>= 1) {
        if (t < s) sh[t] |= sh[t + s];
        __syncthreads();
    }
    if (t == 0) g_is64 = (sh[0] == 0) ? 1 : 0;
}

__global__ void k_wt(const float* __restrict__ W) {
    int i = blockIdx.x * blockDim.x + threadIdx.x;
    if (i < INF * OUTF) {
        int k = i >> 6, o = i & 63;
        g_wt[i] = W[o * INF + k];
    }
}

__global__ void k_init(int N) {
    int i = blockIdx.x * blockDim.x + threadIdx.x;
    if (i < N) { g_den[i] = 0.0f; g_deg[i] = 0; }
}

// ---------------------------------------------------------------------------
// SGEMM: h = x @ W^T + b, fused s1/s2. Tile M=128 x N=64, micro 8x4.
// ---------------------------------------------------------------------------
#define XS_STRIDE 136
__global__ void __launch_bounds__(256) k_gemm(
    const float* __restrict__ x, const float* __restrict__ b,
    const float* __restrict__ a, int N)
{
    __shared__ float Ws[128 * 64];              // 32 KB: half of Wt
    __shared__ float xs[2][16 * XS_STRIDE];     // 17.4 KB

    int t  = threadIdx.x;
    int tx = t & 15;        // n0 = tx*4
    int ty = t >> 4;        // m0 = ty*8
    int base = blockIdx.x * 128;

    float4 acc[8];
#pragma unroll
    for (int i = 0; i < 8; i++) acc[i] = make_float4(0.f, 0.f, 0.f, 0.f);

    // x loader mapping: 512 float4 per chunk, 2 per thread
    int row0 = t >> 1;                 // idx = t*2 .. t*2+1 -> rows t>>1 pairs
    // use idx = t and t+256: row = idx>>2, q = idx&3
#pragma unroll
    for (int half = 0; half < 2; half++) {
        {
            const float4* wp = (const float4*)(g_wt + half * 128 * 64);
            float4* wsp = (float4*)Ws;
#pragma unroll
            for (int i = 0; i < 8; i++) wsp[t + 256 * i] = __ldg(wp + t + 256 * i);
        }
        // Preload first x chunk of this half
#pragma unroll
        for (int r = 0; r < 2; r++) {
            int idx = t + 256 * r;
            int row = idx >> 2, q = idx & 3;
            int node = base + row;
            float4 v = make_float4(0.f, 0.f, 0.f, 0.f);
            if (node < N) v = __ldg((const float4*)(x + (size_t)node * INF) + half * 32 + q);
            float* dst = xs[0];
            dst[(q * 4 + 0) * XS_STRIDE + row] = v.x;
            dst[(q * 4 + 1) * XS_STRIDE + row] = v.y;
            dst[(q * 4 + 2) * XS_STRIDE + row] = v.z;
            dst[(q * 4 + 3) * XS_STRIDE + row] = v.w;
        }
        __syncthreads();

#pragma unroll
        for (int kc = 0; kc < 8; kc++) {
            int buf = kc & 1;
            if (kc < 7) {
#pragma unroll
                for (int r = 0; r < 2; r++) {
                    int idx = t + 256 * r;
                    int row = idx >> 2, q = idx & 3;
                    int node = base + row;
                    float4 v = make_float4(0.f, 0.f, 0.f, 0.f);
                    if (node < N)
                        v = __ldg((const float4*)(x + (size_t)node * INF) + half * 32 + (kc + 1) * 4 + q);
                    float* dst = xs[buf ^ 1];
                    dst[(q * 4 + 0) * XS_STRIDE + row] = v.x;
                    dst[(q * 4 + 1) * XS_STRIDE + row] = v.y;
                    dst[(q * 4 + 2) * XS_STRIDE + row] = v.z;
                    dst[(q * 4 + 3) * XS_STRIDE + row] = v.w;
                }
            }
#pragma unroll
            for (int kk = 0; kk < 16; kk++) {
                float4 bv  = *(const float4*)&Ws[(kc * 16 + kk) * 64 + tx * 4];
                float4 av0 = *(const float4*)&xs[buf][kk * XS_STRIDE + ty * 8];
                float4 av1 = *(const float4*)&xs[buf][kk * XS_STRIDE + ty * 8 + 4];
                acc[0].x += av0.x * bv.x; acc[0].y += av0.x * bv.y; acc[0].z += av0.x * bv.z; acc[0].w += av0.x * bv.w;
                acc[1].x += av0.y * bv.x; acc[1].y += av0.y * bv.y; acc[1].z += av0.y * bv.z; acc[1].w += av0.y * bv.w;
                acc[2].x += av0.z * bv.x; acc[2].y += av0.z * bv.y; acc[2].z += av0.z * bv.z; acc[2].w += av0.z * bv.w;
                acc[3].x += av0.w * bv.x; acc[3].y += av0.w * bv.y; acc[3].z += av0.w * bv.z; acc[3].w += av0.w * bv.w;
                acc[4].x += av1.x * bv.x; acc[4].y += av1.x * bv.y; acc[4].z += av1.x * bv.z; acc[4].w += av1.x * bv.w;
                acc[5].x += av1.y * bv.x; acc[5].y += av1.y * bv.y; acc[5].z += av1.y * bv.z; acc[5].w += av1.y * bv.w;
                acc[6].x += av1.z * bv.x; acc[6].y += av1.z * bv.y; acc[6].z += av1.z * bv.z; acc[6].w += av1.z * bv.w;
                acc[7].x += av1.w * bv.x; acc[7].y += av1.w * bv.y; acc[7].z += av1.w * bv.z; acc[7].w += av1.w * bv.w;
            }
            __syncthreads();
        }
    }

    float4 b4  = __ldg((const float4*)b + tx);
    float4 a1v = __ldg((const float4*)a + tx);
    float4 a2v = __ldg((const float4*)(a + OUTF) + tx);

#pragma unroll
    for (int mi = 0; mi < 8; mi++) {
        int node = base + ty * 8 + mi;
        float4 h;
        h.x = acc[mi].x + b4.x; h.y = acc[mi].y + b4.y;
        h.z = acc[mi].z + b4.z; h.w = acc[mi].w + b4.w;
        if (node < N)
            *((float4*)(g_h + (size_t)node * OUTF) + tx) = h;
        float p1 = h.x * a1v.x + h.y * a1v.y + h.z * a1v.z + h.w * a1v.w;
        float p2 = h.x * a2v.x + h.y * a2v.y + h.z * a2v.z + h.w * a2v.w;
#pragma unroll
        for (int off = 8; off; off >>= 1) {
            p1 += __shfl_xor_sync(0xffffffffu, p1, off);
            p2 += __shfl_xor_sync(0xffffffffu, p2, off);
        }
        if (tx == 0 && node < N) {
            g_s1[node] = p1;
            g_s2[node] = p2;
        }
    }
}

// ---------------------------------------------------------------------------
// Fused edge pass: convert adj, ex = exp(leakyrelu(s1+s2)), denom, src hist.
// ---------------------------------------------------------------------------
__global__ void k_edge12(const void* __restrict__ adj, int E) {
    int i = blockIdx.x * blockDim.x + threadIdx.x;
    if (i >= E) return;
    int s, d;
    if (g_is64) {
        const long long* a = (const long long*)adj;
        s = (int)a[i];
        d = (int)a[(size_t)i + E];
    } else {
        const int* a = (const int*)adj;
        s = a[i];
        d = a[(size_t)i + E];
    }
    g_src[i] = s;
    g_dst[i] = d;
    float e = g_s1[s] + g_s2[d];
    e = e > 0.f ? e : ALPHA * e;
    float ex = __expf(e);
    g_e[i] = ex;
    atomicAdd(&g_den[d], ex);
    atomicAdd(&g_deg[s], 1);
}

// ---------------------------------------------------------------------------
// Exclusive scan of g_deg -> g_ptr (3 kernels)
// ---------------------------------------------------------------------------
__global__ void k_scanA(int N) {
    __shared__ int sh[1024];
    int i = blockIdx.x * 1024 + threadIdx.x;
    int v = (i < N) ? g_deg[i] : 0;
    sh[threadIdx.x] = v;
    __syncthreads();
#pragma unroll
    for (int off = 1; off < 1024; off <<= 1) {
        int add = (threadIdx.x >= off) ? sh[threadIdx.x - off] : 0;
        __syncthreads();
        sh[threadIdx.x] += add;
        __syncthreads();
    }
    if (i < N) g_ptr[i] = sh[threadIdx.x] - v;   // exclusive within block
    if (threadIdx.x == 1023) g_bsum[blockIdx.x] = sh[1023];
}

__global__ void k_scanB(int nb) {
    if (threadIdx.x == 0) {
        int acc = 0;
        for (int b = 0; b < nb; b++) { int t = g_bsum[b]; g_bsum[b] = acc; acc += t; }
    }
}

__global__ void k_scanC(int N) {
    int i = blockIdx.x * blockDim.x + threadIdx.x;
    if (i < N) {
        int p = g_ptr[i] + g_bsum[i >> 10];
        g_ptr[i] = p;
        g_cur[i] = p;
    }
}

// Scatter edges into CSR buckets with precomputed att = ex / den[dst]
__global__ void k_scatter(int E) {
    int i = blockIdx.x * blockDim.x + threadIdx.x;
    if (i >= E) return;
    int s = g_src[i], d = g_dst[i];
    int pos = atomicAdd(&g_cur[s], 1);
    g_sdst[pos] = d;
    g_satt[pos] = g_e[i] / g_den[d];
}

// ---------------------------------------------------------------------------
// Edge pass 3 (CSR): out[n] = elu( sum_j att_j * h[dst_j] ), 16 lanes/node.
// ---------------------------------------------------------------------------
__global__ void __launch_bounds__(256) k_edge3(float* __restrict__ out, int N) {
    int t = threadIdx.x;
    int node = blockIdx.x * 16 + (t >> 4);
    int lane = t & 15;
    if (node >= N) return;
    int start = g_ptr[node];
    int deg   = g_deg[node];
    float4 acc = make_float4(0.f, 0.f, 0.f, 0.f);
    if (deg > 0) {
        int   d   = __ldg(&g_sdst[start]);
        float att = __ldg(&g_satt[start]);
        for (int j = 0; j < deg - 1; j++) {
            int   dn   = __ldg(&g_sdst[start + j + 1]);
            float attn = __ldg(&g_satt[start + j + 1]);
            float4 hv = __ldg((const float4*)(g_h + (size_t)d * OUTF) + lane);
            acc.x += att * hv.x; acc.y += att * hv.y;
            acc.z += att * hv.z; acc.w += att * hv.w;
            d = dn; att = attn;
        }
        float4 hv = __ldg((const float4*)(g_h + (size_t)d * OUTF) + lane);
        acc.x += att * hv.x; acc.y += att * hv.y;
        acc.z += att * hv.z; acc.w += att * hv.w;
    }
    // ELU
    acc.x = acc.x > 0.f ? acc.x : expm1f(acc.x);
    acc.y = acc.y > 0.f ? acc.y : expm1f(acc.y);
    acc.z = acc.z > 0.f ? acc.z : expm1f(acc.z);
    acc.w = acc.w > 0.f ? acc.w : expm1f(acc.w);
    *((float4*)(out + (size_t)node * OUTF) + lane) = acc;
}

extern "C" void kernel_launch(void* const* d_in, const int* in_sizes, int n_in,
                              void* d_out, int out_size)
{
    const void*  adj = d_in[0];
    const float* x   = (const float*)d_in[1];
    const float* W   = (const float*)d_in[2];
    const float* b   = (const float*)d_in[3];
    const float* a   = (const float*)d_in[4];
    float* out = (float*)d_out;

    int E = in_sizes[0] / 2;
    int N = in_sizes[1] / INF;
    int nScanBlocks = (N + 1023) / 1024;

    k_detect<<<1, 256>>>((const int*)adj, E);
    k_wt<<<(INF * OUTF + 255) / 256, 256>>>(W);
    k_init<<<(N + 255) / 256, 256>>>(N);
    k_gemm<<<(N + 127) / 128, 256>>>(x, b, a, N);
    k_edge12<<<(E + 255) / 256, 256>>>(adj, E);
    k_scanA<<<nScanBlocks, 1024>>>(N);
    k_scanB<<<1, 32>>>(nScanBlocks);
    k_scanC<<<(N + 255) / 256, 256>>>(N);
    k_scatter<<<(E + 255) / 256, 256>>>(E);
    k_edge3<<<(N + 15) / 16, 256>>>(out, N);
}